// round 12
// baseline (speedup 1.0000x reference)
#include <cuda_runtime.h>
#include <cstdint>

// ---------------- problem constants ----------------
#define N_ROWS   262144
#define DIMS     64
#define KCODES   1024
#define BM       64
#define THREADS  256
#define GRID     (N_ROWS / BM)              // 4096
#define QOUT     (N_ROWS * DIMS)
#define CAND_CAP 8

// ---------------- smem layout (bytes) ----------------
#define SM_B     0                          // 1024 codes x 80B int8 rows
#define SM_SCN   81920                      // 1024 x float2 (sck, cnorm)
#define SM_CA    90112                      // 64 x 8 x 8B candidates
#define SM_RM    94208                      // 64 u32 keys (+finalize reduce)
#define SM_CT    94464                      // 64 int
#define SM_TK    94720                      // 64 int
#define SM_FLAG  94976                      // 4B
#define SMEM_TOTAL 94992

#define B_STRIDE 80

// ---------------- device globals ----------------
__device__ __align__(16) float2   g_scn[KCODES];          // (sck, 0.5*||c||^2)
__device__ __align__(16) uint4    g_cbi8[KCODES * 4];     // int8 codebook, 64B/code
__device__ unsigned int           g_counts[KCODES];
__device__ float                  g_loss[2];
__device__ int                    g_c1max_bits;           // max ||c||_1
__device__ int                    g_sckmax_bits;          // max sck
__device__ unsigned int           g_done;

// ---------------- helpers ----------------
static __device__ __forceinline__ unsigned fkey(float f) {
    int b = __float_as_int(f);
    return (unsigned)(b >= 0 ? (b | 0x80000000) : ~b);
}
static __device__ __forceinline__ float finv(unsigned k) {
    int b = (k & 0x80000000u) ? (int)(k & 0x7fffffffu) : ~(int)k;
    return __int_as_float(b);
}
static __device__ __forceinline__ void imma16832(
    int& c0, int& c1, int& c2, int& c3,
    uint32_t a0, uint32_t a1, uint32_t a2, uint32_t a3,
    uint32_t b0, uint32_t b1)
{
    asm volatile(
        "mma.sync.aligned.m16n8k32.row.col.s32.s8.s8.s32 "
        "{%0,%1,%2,%3}, {%4,%5,%6,%7}, {%8,%9}, {%0,%1,%2,%3};"
        : "+r"(c0), "+r"(c1), "+r"(c2), "+r"(c3)
        : "r"(a0), "r"(a1), "r"(a2), "r"(a3), "r"(b0), "r"(b1));
}
static __device__ __forceinline__ int clamp127(int v) {
    return v < -127 ? -127 : (v > 127 ? 127 : v);
}
static __device__ __forceinline__ uint32_t q4(float4 v, float inv) {
    int x0 = clamp127(__float2int_rn(v.x * inv));
    int x1 = clamp127(__float2int_rn(v.y * inv));
    int x2 = clamp127(__float2int_rn(v.z * inv));
    int x3 = clamp127(__float2int_rn(v.w * inv));
    return (uint32_t)(x0 & 0xFF) | ((uint32_t)(x1 & 0xFF) << 8) |
           ((uint32_t)(x2 & 0xFF) << 16) | ((uint32_t)(x3 & 0xFF) << 24);
}
// identical expression in both passes -> deterministic score
static __device__ __forceinline__ float cvt_score(int d, float sck, float sx, float cn) {
    return fmaf(__int2float_rn(d) * sck, sx, -cn);
}

// ---------------- prep: resets + int8 codebook + scales + cnorm ----------------
// Low-register two-sweep version (1024 threads/block needs <= 64 regs/thread).
__global__ __launch_bounds__(1024, 1)
void vq_prep(const float* __restrict__ cb) {
    int k = threadIdx.x;   // 1024 threads, 1 block
    g_counts[k] = 0u;
    if (k < 2) g_loss[k] = 0.0f;
    if (k == 2) g_done = 0u;

    const float4* c4 = (const float4*)(cb + (size_t)k * DIMS);
    // sweep 1: stats
    float mx = 0.0f, l1 = 0.0f, ss = 0.0f;
#pragma unroll
    for (int j = 0; j < 16; j++) {
        float4 v = c4[j];
        float ax = fabsf(v.x), ay = fabsf(v.y), az = fabsf(v.z), aw = fabsf(v.w);
        mx = fmaxf(mx, fmaxf(fmaxf(ax, ay), fmaxf(az, aw)));
        l1 += ax + ay + az + aw;
        ss += v.x * v.x + v.y * v.y + v.z * v.z + v.w * v.w;
    }
    mx = fmaxf(mx, 1e-20f);
    float inv = 127.0f / mx;
    float sck = mx * (1.0f / 127.0f);
    // sweep 2: quantize (re-read, low register pressure)
#pragma unroll
    for (int q = 0; q < 4; q++) {
        uint4 p;
        p.x = q4(c4[q * 4 + 0], inv);
        p.y = q4(c4[q * 4 + 1], inv);
        p.z = q4(c4[q * 4 + 2], inv);
        p.w = q4(c4[q * 4 + 3], inv);
        g_cbi8[k * 4 + q] = p;
    }
    g_scn[k] = make_float2(sck, 0.5f * ss);
    atomicMax(&g_c1max_bits, __float_as_int(l1));
    atomicMax(&g_sckmax_bits, __float_as_int(sck));
}

// ---------------- main ----------------
extern __shared__ char smem[];

__global__ __launch_bounds__(THREADS, 2)
void vq_main(const float* __restrict__ inp, const float* __restrict__ cb,
             float* __restrict__ out)
{
    const int tid  = threadIdx.x;
    const int w    = tid >> 5;
    const int lane = tid & 31;
    const int t    = lane & 3;
    const int n    = lane >> 2;
    const int row0 = blockIdx.x * BM;

    float2*   SCN = (float2*)(smem + SM_SCN);
    float2*   CA  = (float2*)(smem + SM_CA);
    unsigned* RM  = (unsigned*)(smem + SM_RM);
    int*      CT  = (int*)(smem + SM_CT);
    int*      TK  = (int*)(smem + SM_TK);
    int*      FLAG = (int*)(smem + SM_FLAG);

    // ---- fills: B int8 (stride 80) + SCN + inits ----
    if (tid < 64) { RM[tid] = 0u; CT[tid] = 0; }
#pragma unroll
    for (int i = 0; i < 16; i++) {
        int idx = tid + i * THREADS;        // 4096 uint4 chunks
        int c = idx >> 2, j = idx & 3;
        uint4 v = g_cbi8[idx];
        *(uint4*)(smem + SM_B + c * B_STRIDE + j * 16) = v;
    }
#pragma unroll
    for (int i = 0; i < 2; i++) {           // SCN: 512 uint4
        int idx = tid + i * THREADS;
        *(uint4*)(smem + SM_SCN + idx * 16) = *(const uint4*)((const char*)g_scn + idx * 16);
    }

    // ---- per-thread A fragments from gmem: quantize int8, row stats ----
    const float C1MAX  = __int_as_float(g_c1max_bits);
    const float SCKMAX = __int_as_float(g_sckmax_bits);
    const int rowblk = (w & 1) * 32;
    const int colq   = (w >> 1) * 256;
    const int ra = rowblk + n, rb = ra + 8, rc = ra + 16, rd = ra + 24;
    const int rows_[4] = { ra, rb, rc, rd };

    uint32_t af[2][8];
    float sxr[4], dl[4];
#pragma unroll
    for (int s = 0; s < 4; s++) {
        const float* xp = inp + (size_t)(row0 + rows_[s]) * DIMS + t * 4;
        float4 v0 = *(const float4*)(xp);
        float4 v1 = *(const float4*)(xp + 16);
        float4 v2 = *(const float4*)(xp + 32);
        float4 v3 = *(const float4*)(xp + 48);
        float mx = 0.0f, l1 = 0.0f;
#pragma unroll
        for (int q = 0; q < 4; q++) {
            float4 vv = (q == 0) ? v0 : (q == 1) ? v1 : (q == 2) ? v2 : v3;
            float ax = fabsf(vv.x), ay = fabsf(vv.y), az = fabsf(vv.z), aw = fabsf(vv.w);
            mx = fmaxf(mx, fmaxf(fmaxf(ax, ay), fmaxf(az, aw)));
            l1 += ax + ay + az + aw;
        }
        mx = fmaxf(mx, __shfl_xor_sync(0xffffffffu, mx, 1));
        mx = fmaxf(mx, __shfl_xor_sync(0xffffffffu, mx, 2));
        l1 += __shfl_xor_sync(0xffffffffu, l1, 1);
        l1 += __shfl_xor_sync(0xffffffffu, l1, 2);
        mx = fmaxf(mx, 1e-20f);
        float inv = 127.0f / mx;
        float sx  = mx * (1.0f / 127.0f);
        sxr[s] = sx;
        // certified bound: 0.5*sck*||x||_1 + 0.5*sx*||c||_1 + 48*sx*sck (+slack)
        dl[s]  = 0.5f * sx * C1MAX + 0.5f * SCKMAX * l1 + 48.0f * sx * SCKMAX + 1e-3f;
        int base = (s >> 1) * 4 + (s & 1);
        af[0][base]     = q4(v0, inv);      // ks0, k=4t..4t+3
        af[0][base + 2] = q4(v1, inv);      // ks0, k=16+4t
        af[1][base]     = q4(v2, inv);      // ks1, k=32+4t
        af[1][base + 2] = q4(v3, inv);      // ks1, k=48+4t
    }
    __syncthreads();

    // ================= PASS 1: exact approx-max per row =================
    float gma[8], gmb[8], gmc[8], gmd[8];
#pragma unroll
    for (int g = 0; g < 8; g++) {
        gma[g] = -3.4e38f; gmb[g] = -3.4e38f;
        gmc[g] = -3.4e38f; gmd[g] = -3.4e38f;
    }

#pragma unroll 4
    for (int j = 0; j < 32; ++j) {
        const int col0 = colq + j * 8 + t * 2;
        int d00 = 0, d01 = 0, d02 = 0, d03 = 0;
        int d10 = 0, d11 = 0, d12 = 0, d13 = 0;
        const char* bp = smem + SM_B + (colq + j * 8 + n) * B_STRIDE + t * 4;
#pragma unroll
        for (int ks = 0; ks < 2; ks++) {
            uint32_t b0 = *(const uint32_t*)(bp + ks * 32);
            uint32_t b1 = *(const uint32_t*)(bp + ks * 32 + 16);
            imma16832(d00, d01, d02, d03,
                      af[ks][0], af[ks][1], af[ks][2], af[ks][3], b0, b1);
            imma16832(d10, d11, d12, d13,
                      af[ks][4], af[ks][5], af[ks][6], af[ks][7], b0, b1);
        }
        float4 sc = *(const float4*)((const char*)SCN + col0 * 8);  // sck0,cn0,sck1,cn1
        float v00 = cvt_score(d00, sc.x, sxr[0], sc.y);
        float v01 = cvt_score(d01, sc.z, sxr[0], sc.w);
        float v02 = cvt_score(d02, sc.x, sxr[1], sc.y);
        float v03 = cvt_score(d03, sc.z, sxr[1], sc.w);
        float v10 = cvt_score(d10, sc.x, sxr[2], sc.y);
        float v11 = cvt_score(d11, sc.z, sxr[2], sc.w);
        float v12 = cvt_score(d12, sc.x, sxr[3], sc.y);
        float v13 = cvt_score(d13, sc.z, sxr[3], sc.w);
        int g = j >> 2;
        gma[g] = fmaxf(gma[g], fmaxf(v00, v01));
        gmb[g] = fmaxf(gmb[g], fmaxf(v02, v03));
        gmc[g] = fmaxf(gmc[g], fmaxf(v10, v11));
        gmd[g] = fmaxf(gmd[g], fmaxf(v12, v13));
    }

    // quad-combine group maxima + publish row maxima
    float rma = -3.4e38f, rmb = -3.4e38f, rmc = -3.4e38f, rmd = -3.4e38f;
#pragma unroll
    for (int g = 0; g < 8; g++) {
        gma[g] = fmaxf(gma[g], __shfl_xor_sync(0xffffffffu, gma[g], 1));
        gma[g] = fmaxf(gma[g], __shfl_xor_sync(0xffffffffu, gma[g], 2));
        gmb[g] = fmaxf(gmb[g], __shfl_xor_sync(0xffffffffu, gmb[g], 1));
        gmb[g] = fmaxf(gmb[g], __shfl_xor_sync(0xffffffffu, gmb[g], 2));
        gmc[g] = fmaxf(gmc[g], __shfl_xor_sync(0xffffffffu, gmc[g], 1));
        gmc[g] = fmaxf(gmc[g], __shfl_xor_sync(0xffffffffu, gmc[g], 2));
        gmd[g] = fmaxf(gmd[g], __shfl_xor_sync(0xffffffffu, gmd[g], 1));
        gmd[g] = fmaxf(gmd[g], __shfl_xor_sync(0xffffffffu, gmd[g], 2));
        rma = fmaxf(rma, gma[g]); rmb = fmaxf(rmb, gmb[g]);
        rmc = fmaxf(rmc, gmc[g]); rmd = fmaxf(rmd, gmd[g]);
    }
    if (t == 0) {
        atomicMax(&RM[ra], fkey(rma));
        atomicMax(&RM[rb], fkey(rmb));
        atomicMax(&RM[rc], fkey(rmc));
        atomicMax(&RM[rd], fkey(rmd));
    }
    __syncthreads();

    // ================= PASS 2: fixed-threshold candidate collection =================
    const float thra = finv(RM[ra]) - dl[0];
    const float thrb = finv(RM[rb]) - dl[1];
    const float thrc = finv(RM[rc]) - dl[2];
    const float thrd = finv(RM[rd]) - dl[3];

#define PUSH2(val, row, thr, col) do {                                      \
        if ((val) >= (thr)) {                                               \
            int p = atomicAdd(&CT[row], 1);                                 \
            if (p < CAND_CAP)                                               \
                CA[(row) * CAND_CAP + p] =                                  \
                    make_float2((val), __int_as_float(col));                \
        }                                                                   \
    } while (0)

    for (int g = 0; g < 8; g++) {
        bool need = (gma[g] >= thra) || (gmb[g] >= thrb) ||
                    (gmc[g] >= thrc) || (gmd[g] >= thrd);
        if (!__any_sync(0xffffffffu, need)) continue;
#pragma unroll
        for (int jj = 0; jj < 4; jj++) {
            int j = g * 4 + jj;
            const int col0 = colq + j * 8 + t * 2;
            int d00 = 0, d01 = 0, d02 = 0, d03 = 0;
            int d10 = 0, d11 = 0, d12 = 0, d13 = 0;
            const char* bp = smem + SM_B + (colq + j * 8 + n) * B_STRIDE + t * 4;
#pragma unroll
            for (int ks = 0; ks < 2; ks++) {
                uint32_t b0 = *(const uint32_t*)(bp + ks * 32);
                uint32_t b1 = *(const uint32_t*)(bp + ks * 32 + 16);
                imma16832(d00, d01, d02, d03,
                          af[ks][0], af[ks][1], af[ks][2], af[ks][3], b0, b1);
                imma16832(d10, d11, d12, d13,
                          af[ks][4], af[ks][5], af[ks][6], af[ks][7], b0, b1);
            }
            float4 sc = *(const float4*)((const char*)SCN + col0 * 8);
            float v00 = cvt_score(d00, sc.x, sxr[0], sc.y);
            float v01 = cvt_score(d01, sc.z, sxr[0], sc.w);
            float v02 = cvt_score(d02, sc.x, sxr[1], sc.y);
            float v03 = cvt_score(d03, sc.z, sxr[1], sc.w);
            float v10 = cvt_score(d10, sc.x, sxr[2], sc.y);
            float v11 = cvt_score(d11, sc.z, sxr[2], sc.w);
            float v12 = cvt_score(d12, sc.x, sxr[3], sc.y);
            float v13 = cvt_score(d13, sc.z, sxr[3], sc.w);
            PUSH2(v00, ra, thra, col0); PUSH2(v01, ra, thra, col0 + 1);
            PUSH2(v02, rb, thrb, col0); PUSH2(v03, rb, thrb, col0 + 1);
            PUSH2(v10, rc, thrc, col0); PUSH2(v11, rc, thrc, col0 + 1);
            PUSH2(v12, rd, thrd, col0); PUSH2(v13, rd, thrd, col0 + 1);
        }
    }
#undef PUSH2
    __syncthreads();

    // ---- exact fp32 rescore (1 thread per row, x from gmem) ----
    if (tid < 64) {
        int r = tid;
        int nc = CT[r];
        const float4* xr = (const float4*)(inp + (size_t)(row0 + r) * DIMS);
        float bestS = -3.4e38f;
        int   bestI = KCODES;
        if (nc <= CAND_CAP) {
            for (int i = 0; i < nc; i++) {
                float2 ce = CA[r * CAND_CAP + i];
                int ix = __float_as_int(ce.y);
                const float4* c4 = (const float4*)(cb + (size_t)ix * DIMS);
                float a0 = 0.f, a1 = 0.f, a2 = 0.f, a3 = 0.f;
#pragma unroll
                for (int q = 0; q < 16; q++) {
                    float4 cv = c4[q];
                    float4 xv = xr[q];
                    a0 = fmaf(xv.x, cv.x, a0);
                    a1 = fmaf(xv.y, cv.y, a1);
                    a2 = fmaf(xv.z, cv.z, a2);
                    a3 = fmaf(xv.w, cv.w, a3);
                }
                float s = (a0 + a1) + (a2 + a3) - SCN[ix].y;
                if (s > bestS || (s == bestS && ix < bestI)) { bestS = s; bestI = ix; }
            }
        } else {
            // overflow fallback (rare): exact full scan
            for (int ix = 0; ix < KCODES; ix++) {
                const float4* c4 = (const float4*)(cb + (size_t)ix * DIMS);
                float a0 = 0.f, a1 = 0.f, a2 = 0.f, a3 = 0.f;
#pragma unroll
                for (int q = 0; q < 16; q++) {
                    float4 cv = c4[q];
                    float4 xv = xr[q];
                    a0 = fmaf(xv.x, cv.x, a0);
                    a1 = fmaf(xv.y, cv.y, a1);
                    a2 = fmaf(xv.z, cv.z, a2);
                    a3 = fmaf(xv.w, cv.w, a3);
                }
                float s = (a0 + a1) + (a2 + a3) - SCN[ix].y;
                if (s > bestS) { bestS = s; bestI = ix; }
            }
        }
        TK[r] = bestI;
        out[QOUT + row0 + r] = (float)bestI;
        atomicAdd(&g_counts[bestI], 1u);
    }
    __syncthreads();

    // ---- quantized + straight-through + losses (cooperative, coalesced) ----
    float esum = 0.0f, qsum = 0.0f;
#pragma unroll
    for (int i = 0; i < 4; i++) {
        int idx = tid + i * THREADS;        // 1024 float4 chunks (64 rows x 16)
        int r = idx >> 4, q = idx & 15;
        int ix = TK[r];
        float4 cv = *(const float4*)(cb + (size_t)ix * DIMS + q * 4);
        float4 xv = *(const float4*)(inp + (size_t)(row0 + r) * DIMS + q * 4);
        float d0v = cv.x - xv.x, d1v = cv.y - xv.y, d2v = cv.z - xv.z, d3v = cv.w - xv.w;
        float q0 = xv.x + d0v, q1 = xv.y + d1v, q2 = xv.z + d2v, q3 = xv.w + d3v;
        float e0 = q0 - xv.x, e1 = q1 - xv.y, e2 = q2 - xv.z, e3 = q3 - xv.w;
        esum += e0 * e0 + e1 * e1 + e2 * e2 + e3 * e3;
        qsum += d0v * d0v + d1v * d1v + d2v * d2v + d3v * d3v;
        *(float4*)(out + (size_t)(row0 + r) * DIMS + q * 4) = make_float4(q0, q1, q2, q3);
    }
#pragma unroll
    for (int off = 16; off > 0; off >>= 1) {
        esum += __shfl_xor_sync(0xffffffffu, esum, off);
        qsum += __shfl_xor_sync(0xffffffffu, qsum, off);
    }
    if (lane == 0) {
        atomicAdd(&g_loss[0], esum);
        atomicAdd(&g_loss[1], qsum);
    }

    // ---- last-CTA finalize (perplexity + scalar losses) ----
    if (tid == 0) {
        __threadfence();
        *FLAG = (atomicAdd(&g_done, 1u) == GRID - 1) ? 1 : 0;
    }
    __syncthreads();
    if (*FLAG) {
        volatile unsigned* vc = g_counts;
        float part = 0.0f;
#pragma unroll
        for (int i = 0; i < 4; i++) {
            float p = (float)vc[tid + i * THREADS] / (float)N_ROWS;
            part += -p * logf(p + 1e-10f);
        }
#pragma unroll
        for (int off = 16; off > 0; off >>= 1)
            part += __shfl_xor_sync(0xffffffffu, part, off);
        float* red = (float*)RM;            // reuse: 8 warp partials
        if (lane == 0) red[w] = part;
        __syncthreads();
        if (tid == 0) {
            float H = 0.0f;
#pragma unroll
            for (int i = 0; i < 8; i++) H += red[i];
            volatile float* vl = g_loss;
            float inv = 1.0f / (float)((long long)N_ROWS * DIMS);
            float e_mean = vl[0] * inv;
            float q_mean = vl[1] * inv;
            float commit = 0.25f * e_mean;
            out[QOUT + N_ROWS + 0] = commit + q_mean;
            out[QOUT + N_ROWS + 1] = commit;
            out[QOUT + N_ROWS + 2] = q_mean;
            out[QOUT + N_ROWS + 3] = expf(H);
        }
    }
}

extern "C" void kernel_launch(void* const* d_in, const int* in_sizes, int n_in,
                              void* d_out, int out_size)
{
    const float* inp = (const float*)d_in[0];
    const float* cb  = (const float*)d_in[1];
    float* out = (float*)d_out;

    cudaFuncSetAttribute(vq_main, cudaFuncAttributeMaxDynamicSharedMemorySize, SMEM_TOTAL);

    vq_prep<<<1, 1024>>>(cb);
    vq_main<<<GRID, THREADS, SMEM_TOTAL>>>(inp, cb, out);
}